// round 1
// baseline (speedup 1.0000x reference)
#include <cuda_runtime.h>
#include <math.h>

#define BB 512
#define RR 1152
#define CC 10
#define OO 16
#define CO 160
#define II 8

// Scratch (sanctioned: __device__ globals, no cudaMalloc anywhere)
__device__ float g_uhat[(size_t)BB * RR * CO];  // [b][r][co], 377 MB
__device__ float g_va[BB * CO];                  // v0
__device__ float g_vb[BB * CO];                  // v0 + v1

// ---------------------------------------------------------------------------
// K1: u_hat[b,r,c,o] = sum_i W[r,c,o,i] * x[b,r,i]
// Block per r (W for this r lives in registers, reused across all 512 b).
// ---------------------------------------------------------------------------
__global__ __launch_bounds__(256) void uhat_kernel(const float* __restrict__ x,
                                                   const float* __restrict__ W) {
    const int r   = blockIdx.x;
    const int tid = threadIdx.x;
    const int w   = tid >> 5;
    const int l   = tid & 31;

    __shared__ float xs[BB * II];  // 16 KB: x[:, r, :]

    // Cooperative stage of x[:, r, :] (float4)
    const float4* X4  = reinterpret_cast<const float4*>(x);
    float4*       xs4 = reinterpret_cast<float4*>(xs);
    for (int idx = tid; idx < BB * II / 4; idx += 256) {
        int b = idx >> 1, part = idx & 1;
        xs4[idx] = X4[(size_t)b * (RR * II / 4) + r * 2 + part];
    }

    // W row for this r: lane l owns co = l + 32j, j=0..4 (40 floats in regs)
    float4 wr[5][2];
    const float4* W4 = reinterpret_cast<const float4*>(W + (size_t)r * CO * II);
#pragma unroll
    for (int j = 0; j < 5; j++) {
        int co = l + 32 * j;
        wr[j][0] = W4[co * 2 + 0];
        wr[j][1] = W4[co * 2 + 1];
    }
    __syncthreads();

    for (int b = w; b < BB; b += 8) {
        const float4 xa = xs4[b * 2 + 0];
        const float4 xb = xs4[b * 2 + 1];
        float* outp = g_uhat + ((size_t)b * RR + r) * CO;
#pragma unroll
        for (int j = 0; j < 5; j++) {
            float u = wr[j][0].x * xa.x + wr[j][0].y * xa.y +
                      wr[j][0].z * xa.z + wr[j][0].w * xa.w +
                      wr[j][1].x * xb.x + wr[j][1].y * xb.y +
                      wr[j][1].z * xb.z + wr[j][1].w * xb.w;
            outp[l + 32 * j] = u;
        }
    }
}

// ---------------------------------------------------------------------------
// K2: one routing pass, fused with bias + squash epilogue. Block per b.
//   mode 0: c_ij uniform (=0.1). writes v0 -> g_va
//   mode 1: logits = u.v0 (g_va). writes v0+v1 -> g_vb
//   mode 2: logits = u.(v0+v1) (g_vb). writes v2 -> dout
// Lane l of each warp owns co = l + 32j (j=0..4); warp handles r = w + 8k.
// Within a j-slot, lanes 0-15 are (c=2j, o=0..15), lanes 16-31 are (c=2j+1).
// ---------------------------------------------------------------------------
__global__ __launch_bounds__(256) void route_kernel(const float* __restrict__ bias,
                                                    float* __restrict__ dout,
                                                    int mode) {
    const int b   = blockIdx.x;
    const int tid = threadIdx.x;
    const int w   = tid >> 5;
    const int l   = tid & 31;

    __shared__ float v_sh[CO];
    __shared__ float s_part[8][CO];

    const float* vin  = (mode == 1) ? g_va : g_vb;
    float*       vout = (mode == 0) ? g_va : ((mode == 1) ? g_vb : dout);

    if (tid < CO) v_sh[tid] = (mode > 0) ? vin[b * CO + tid] : 0.0f;
    __syncthreads();

    float vreg[5];
#pragma unroll
    for (int j = 0; j < 5; j++) vreg[j] = v_sh[l + 32 * j];

    float acc[5] = {0.f, 0.f, 0.f, 0.f, 0.f};
    const float* ub = g_uhat + (size_t)b * RR * CO;

    for (int r = w; r < RR; r += 8) {
        const float* up = ub + (size_t)r * CO;
        float u[5];
#pragma unroll
        for (int j = 0; j < 5; j++) u[j] = up[l + 32 * j];

        if (mode == 0) {
#pragma unroll
            for (int j = 0; j < 5; j++) acc[j] += u[j];
        } else {
            // logits lg[j] for c = 2j + (l>=16): dot over o via width-16 butterfly
            float lg[5];
#pragma unroll
            for (int j = 0; j < 5; j++) {
                float p = u[j] * vreg[j];
                p += __shfl_xor_sync(0xffffffffu, p, 8, 16);
                p += __shfl_xor_sync(0xffffffffu, p, 4, 16);
                p += __shfl_xor_sync(0xffffffffu, p, 2, 16);
                p += __shfl_xor_sync(0xffffffffu, p, 1, 16);
                lg[j] = p;
            }
            // softmax over the 10 capsules (own parity holds 5, other via xor 16)
            float m = lg[0];
#pragma unroll
            for (int j = 1; j < 5; j++) m = fmaxf(m, lg[j]);
            m = fmaxf(m, __shfl_xor_sync(0xffffffffu, m, 16));
            float e[5], ssum = 0.f;
#pragma unroll
            for (int j = 0; j < 5; j++) {
                e[j] = __expf(lg[j] - m);
                ssum += e[j];
            }
            ssum += __shfl_xor_sync(0xffffffffu, ssum, 16);
            float inv = 1.0f / ssum;
#pragma unroll
            for (int j = 0; j < 5; j++) acc[j] += (e[j] * inv) * u[j];
        }
    }

    // deterministic block reduction of s over the 8 warps
#pragma unroll
    for (int j = 0; j < 5; j++) s_part[w][l + 32 * j] = acc[j];
    __syncthreads();

    if (tid < CO) {
        float s = 0.f;
#pragma unroll
        for (int k = 0; k < 8; k++) s += s_part[k][tid];
        float scale = (mode == 0) ? 0.1f : 1.0f;
        s = s * scale + bias[tid];
        s_part[0][tid] = s;  // reuse smem for squash norm
    }
    __syncthreads();

    if (tid < CO) {
        int c = tid >> 4;
        float nsq = 0.f;
#pragma unroll
        for (int o = 0; o < OO; o++) {
            float t = s_part[0][c * OO + o];
            nsq += t * t;
        }
        float nrm = sqrtf(nsq);
        float val = s_part[0][tid] * (nrm / (1.0f + nsq + 1e-8f));
        if (mode == 1)
            vout[b * CO + tid] = v_sh[tid] + val;  // vsum = v0 + v1 for pass 2
        else
            vout[b * CO + tid] = val;              // v0, or final v2 -> dout
    }
}

// ---------------------------------------------------------------------------
extern "C" void kernel_launch(void* const* d_in, const int* in_sizes, int n_in,
                              void* d_out, int out_size) {
    const float* x    = (const float*)d_in[0];  // [512,1152,8]
    const float* W    = (const float*)d_in[1];  // [1152,10,16,8]
    const float* bias = (const float*)d_in[2];  // [1,1,10,16]
    float* out = (float*)d_out;                 // [512,10,16]

    uhat_kernel<<<RR, 256>>>(x, W);
    route_kernel<<<BB, 256>>>(bias, out, 0);  // iter 0: uniform c, writes v0
    route_kernel<<<BB, 256>>>(bias, out, 1);  // iter 1: dot v0, writes v0+v1
    route_kernel<<<BB, 256>>>(bias, out, 2);  // iter 2: dot (v0+v1), writes v2
}

// round 2
// speedup vs baseline: 1.9631x; 1.9631x over previous
#include <cuda_runtime.h>
#include <cuda_fp16.h>
#include <math.h>

#define BB 512
#define RR 1152
#define CC 10
#define OO 16
#define CO 160
#define II 8
#define CHUNK 8              // rows per warp iteration
#define NCHUNK (RR / CHUNK)  // 144

// Scratch (__device__ globals, sanctioned). u_hat stored fp16: 189 MB.
__device__ uint4 g_uhat4[(size_t)BB * RR * CO / 8];  // [b][r][co] halfs, uint4-aligned
__device__ float g_va[BB * CO];                      // v0
__device__ float g_vb[BB * CO];                      // v0 + v1

// ---------------------------------------------------------------------------
// K1: u_hat[b,r,c,o] = sum_i W[r,c,o,i] * x[b,r,i], stored fp16 [b][r][co].
// Block per r; W for this r register-resident; x[:,r,:] staged in smem.
// Lane owns co-PAIRS so stores are packed half2 (coalesced 128B per warp).
//   slot s=0: pair p=l ; s=1: p=32+l ; s=2: p=64+l (lanes l<16 only)
// ---------------------------------------------------------------------------
__global__ __launch_bounds__(256) void uhat_kernel(const float* __restrict__ x,
                                                   const float* __restrict__ W) {
    const int r = blockIdx.x;
    const int tid = threadIdx.x;
    const int w = tid >> 5;
    const int l = tid & 31;

    __shared__ float4 xs4[BB * 2];  // 16 KB: x[:, r, :]

    for (int idx = tid; idx < BB * 2; idx += 256)
        xs4[idx] = reinterpret_cast<const float4*>(x)[(size_t)(idx >> 1) * (RR * 2) + r * 2 + (idx & 1)];

    // W for owned pairs: per slot 16 floats (2 co x 8 i)
    const float4* W4 = reinterpret_cast<const float4*>(W + (size_t)r * CO * II);
    float4 wA[3][4];
#pragma unroll
    for (int s = 0; s < 3; s++) {
        if (s < 2 || l < 16) {
            int p = s * 32 + l;
#pragma unroll
            for (int q = 0; q < 4; q++) wA[s][q] = W4[p * 4 + q];
        }
    }
    __syncthreads();

    for (int b = w; b < BB; b += 8) {
        const float4 xa = xs4[b * 2 + 0];
        const float4 xb = xs4[b * 2 + 1];
        __half2* outp = reinterpret_cast<__half2*>(g_uhat4 + ((size_t)b * RR + r) * (CO / 8));
#pragma unroll
        for (int s = 0; s < 3; s++) {
            if (s < 2 || l < 16) {
                float u0 = wA[s][0].x * xa.x + wA[s][0].y * xa.y + wA[s][0].z * xa.z + wA[s][0].w * xa.w +
                           wA[s][1].x * xb.x + wA[s][1].y * xb.y + wA[s][1].z * xb.z + wA[s][1].w * xb.w;
                float u1 = wA[s][2].x * xa.x + wA[s][2].y * xa.y + wA[s][2].z * xa.z + wA[s][2].w * xa.w +
                           wA[s][3].x * xb.x + wA[s][3].y * xb.y + wA[s][3].z * xb.z + wA[s][3].w * xb.w;
                outp[s * 32 + l] = __floats2half2_rn(u0, u1);
            }
        }
    }
}

// ---------------------------------------------------------------------------
// Routing pass, fused bias+squash. Block per b, 8 warps; warp processes
// 8-row chunks (2560B = 5 x 512B coalesced LDG.128).
// Lane l, slot j: task t = l+32j in [0,160): row=t/20 (within chunk),
// q=t%20 (q=c*2+half), covering o in [8*half, 8*half+8) of capsule c.
// Dot over o: 4 HFMA2 in-register + ONE shfl_xor(1) to join halves.
// Softmax over c: bare exp (logits bounded), per-warp smem sum exchange.
//   MODE 0: uniform c=0.1 -> writes v0 to g_va
//   MODE 1: logits u.v0   -> writes v0+v1 to g_vb
//   MODE 2: logits u.(v0+v1) -> writes v2 to dout
// ---------------------------------------------------------------------------
template <int MODE>
__global__ __launch_bounds__(256) void route_kernel(const float* __restrict__ bias,
                                                    float* __restrict__ dout) {
    const int b = blockIdx.x;
    const int tid = threadIdx.x;
    const int w = tid >> 5;
    const int l = tid & 31;

    __shared__ float part[8][CHUNK][CO];  // 40 KB per-warp partials
    __shared__ float e_sm[8][80];         // per-warp exp(logit) exchange
    __shared__ float inv_sm[8][8];        // per-warp per-row 1/sum
    __shared__ float v_sm[CO];

    if (MODE > 0) {
        const float* vin = (MODE == 1) ? g_va : g_vb;
        if (tid < CO) v_sm[tid] = vin[b * CO + tid];
    }
    __syncthreads();

    // loop-invariant per-slot constants
    int rowj[5], qj[5];
    __half2 v2[5][4];
#pragma unroll
    for (int j = 0; j < 5; j++) {
        int t = l + 32 * j;
        rowj[j] = t / 20;
        qj[j] = t % 20;
        if (MODE > 0) {
            int ob = qj[j] * 8;
#pragma unroll
            for (int k = 0; k < 4; k++)
                v2[j][k] = __floats2half2_rn(v_sm[ob + 2 * k], v_sm[ob + 2 * k + 1]);
        }
    }

    float acc[5][8];
#pragma unroll
    for (int j = 0; j < 5; j++)
#pragma unroll
        for (int k = 0; k < 8; k++) acc[j][k] = 0.0f;

    const uint4* ubase = g_uhat4 + (size_t)b * RR * (CO / 8);

    for (int ch = w; ch < NCHUNK; ch += 8) {
        const uint4* p = ubase + ch * (CHUNK * CO / 8);  // 160 uint4 per chunk
        uint4 uu[5];
#pragma unroll
        for (int j = 0; j < 5; j++) uu[j] = p[l + 32 * j];

        float wgt[5];
        if (MODE > 0) {
            float e[5];
#pragma unroll
            for (int j = 0; j < 5; j++) {
                const __half2* u2 = reinterpret_cast<const __half2*>(&uu[j]);
                __half2 p2 = __hmul2(u2[0], v2[j][0]);
                p2 = __hfma2(u2[1], v2[j][1], p2);
                p2 = __hfma2(u2[2], v2[j][2], p2);
                p2 = __hfma2(u2[3], v2[j][3], p2);
                unsigned pu = __shfl_xor_sync(0xffffffffu, *reinterpret_cast<unsigned*>(&p2), 1);
                p2 = __hadd2(p2, *reinterpret_cast<__half2*>(&pu));
                float lg = __low2float(p2) + __high2float(p2);
                e[j] = __expf(lg);  // no max-sub: |lg| is small by construction
            }
            if (!(l & 1)) {
#pragma unroll
                for (int j = 0; j < 5; j++) e_sm[w][(l >> 1) + 16 * j] = e[j];
            }
            __syncwarp();
            if (l < 8) {
                float s = 0.0f;
#pragma unroll
                for (int i = 0; i < 10; i++) s += e_sm[w][l * 10 + i];
                inv_sm[w][l] = 1.0f / s;
            }
            __syncwarp();
#pragma unroll
            for (int j = 0; j < 5; j++) wgt[j] = e[j] * inv_sm[w][rowj[j]];
        }

#pragma unroll
        for (int j = 0; j < 5; j++) {
            const __half2* u2 = reinterpret_cast<const __half2*>(&uu[j]);
#pragma unroll
            for (int k = 0; k < 4; k++) {
                float2 uf = __half22float2(u2[k]);
                if (MODE == 0) {
                    acc[j][2 * k] += uf.x;
                    acc[j][2 * k + 1] += uf.y;
                } else {
                    acc[j][2 * k] += wgt[j] * uf.x;
                    acc[j][2 * k + 1] += wgt[j] * uf.y;
                }
            }
        }
    }

    // flush per-warp partials: co = q*8 + k
#pragma unroll
    for (int j = 0; j < 5; j++)
#pragma unroll
        for (int k = 0; k < 8; k++) part[w][rowj[j]][qj[j] * 8 + k] = acc[j][k];
    __syncthreads();

    if (tid < CO) {
        float s = 0.0f;
#pragma unroll
        for (int w2 = 0; w2 < 8; w2++)
#pragma unroll
            for (int r2 = 0; r2 < CHUNK; r2++) s += part[w2][r2][tid];
        if (MODE == 0) s *= 0.1f;  // softmax(0) = 1/10 exactly
        s += bias[tid];
        part[0][0][tid] = s;  // column `tid` is exclusively this thread's
    }
    __syncthreads();

    if (tid < CO) {
        int c = tid >> 4;
        float nsq = 0.0f;
#pragma unroll
        for (int o = 0; o < OO; o++) {
            float t = part[0][0][c * OO + o];
            nsq += t * t;
        }
        float val = part[0][0][tid] * (sqrtf(nsq) / (1.0f + nsq + 1e-8f));
        if (MODE == 0) g_va[b * CO + tid] = val;
        else if (MODE == 1) g_vb[b * CO + tid] = v_sm[tid] + val;  // vsum = v0+v1
        else dout[b * CO + tid] = val;
    }
}

// ---------------------------------------------------------------------------
extern "C" void kernel_launch(void* const* d_in, const int* in_sizes, int n_in,
                              void* d_out, int out_size) {
    const float* x    = (const float*)d_in[0];  // [512,1152,8]
    const float* W    = (const float*)d_in[1];  // [1152,10,16,8]
    const float* bias = (const float*)d_in[2];  // [1,1,10,16]
    float* out = (float*)d_out;                 // [512,10,16]

    uhat_kernel<<<RR, 256>>>(x, W);
    route_kernel<0><<<BB, 256>>>(bias, out);
    route_kernel<1><<<BB, 256>>>(bias, out);
    route_kernel<2><<<BB, 256>>>(bias, out);
}